// round 1
// baseline (speedup 1.0000x reference)
#include <cuda_runtime.h>
#include <cuda_bf16.h>
#include <math.h>

// ---------------- problem constants ----------------
#define B_    2
#define S_    1024
#define H_    2048
#define NK_   16
#define NV_   32
#define DK_   128
#define DV_   128
#define QKVZW 12288     // 2*KDIM + 2*VDIM
#define KDIM_ 2048
#define VDIM_ 4096
#define TOK_  (B_*S_)   // 2048

// ---------------- scratch (device globals; no cudaMalloc allowed) ----------
__device__ float g_qkvz[(size_t)TOK_ * QKVZW];         // [B*S, 12288]
__device__ float g_ba  [(size_t)TOK_ * 64];            // [B*S, 64]
__device__ float g_q   [(size_t)B_ * NK_ * S_ * DK_];  // [B,16,S,128] normalized*dk^-0.5
__device__ float g_k   [(size_t)B_ * NK_ * S_ * DK_];  // [B,16,S,128] normalized
__device__ float g_v   [(size_t)B_ * NV_ * S_ * DV_];  // [B,32,S,128]
__device__ float g_eg  [(size_t)B_ * NV_ * S_];        // exp(g)
__device__ float g_beta[(size_t)B_ * NV_ * S_];
__device__ float g_o   [(size_t)B_ * NV_ * S_ * DV_];  // scan output [B,32,S,128]
__device__ float g_y   [(size_t)TOK_ * VDIM_];         // post-rmsnorm [B*S, 4096]

// ---------------- fp32 tiled SGEMM: C[M,N] = A[M,K] * B[K,N] ----------------
// 128x128 block tile, BK=16, 256 threads, 8x8 per thread. M,N%128==0, K%16==0.
__global__ __launch_bounds__(256) void sgemm128(const float* __restrict__ A,
                                                const float* __restrict__ B,
                                                float* __restrict__ C,
                                                int M, int N, int K)
{
    __shared__ float As[16][128];   // transposed: As[k][m]
    __shared__ float Bs[16][128];   // Bs[k][n]

    int tid = threadIdx.x;
    int bm = blockIdx.y * 128;
    int bn = blockIdx.x * 128;
    int tm = (tid >> 4) * 8;
    int tn = (tid & 15) * 8;

    int arow = tid >> 2;            // 0..63
    int ak0  = (tid & 3) * 4;       // 0,4,8,12
    int bk0  = tid >> 5;            // 0..7
    int bn0  = (tid & 31) * 4;

    float acc[8][8];
#pragma unroll
    for (int i = 0; i < 8; i++)
#pragma unroll
        for (int j = 0; j < 8; j++) acc[i][j] = 0.f;

    for (int kt = 0; kt < K; kt += 16) {
        float4 a0 = *(const float4*)&A[(size_t)(bm + arow)      * K + kt + ak0];
        float4 a1 = *(const float4*)&A[(size_t)(bm + arow + 64) * K + kt + ak0];
        float4 b0 = *(const float4*)&B[(size_t)(kt + bk0)     * N + bn + bn0];
        float4 b1 = *(const float4*)&B[(size_t)(kt + bk0 + 8) * N + bn + bn0];
        __syncthreads();
        As[ak0 + 0][arow] = a0.x; As[ak0 + 1][arow] = a0.y;
        As[ak0 + 2][arow] = a0.z; As[ak0 + 3][arow] = a0.w;
        As[ak0 + 0][arow + 64] = a1.x; As[ak0 + 1][arow + 64] = a1.y;
        As[ak0 + 2][arow + 64] = a1.z; As[ak0 + 3][arow + 64] = a1.w;
        *(float4*)&Bs[bk0][bn0]     = b0;
        *(float4*)&Bs[bk0 + 8][bn0] = b1;
        __syncthreads();
#pragma unroll
        for (int k = 0; k < 16; k++) {
            float4 t0 = *(float4*)&As[k][tm];
            float4 t1 = *(float4*)&As[k][tm + 4];
            float4 u0 = *(float4*)&Bs[k][tn];
            float4 u1 = *(float4*)&Bs[k][tn + 4];
            float a_[8] = {t0.x, t0.y, t0.z, t0.w, t1.x, t1.y, t1.z, t1.w};
            float b_[8] = {u0.x, u0.y, u0.z, u0.w, u1.x, u1.y, u1.z, u1.w};
#pragma unroll
            for (int i = 0; i < 8; i++)
#pragma unroll
                for (int j = 0; j < 8; j++) acc[i][j] += a_[i] * b_[j];
        }
    }
#pragma unroll
    for (int i = 0; i < 8; i++) {
        float4 r0 = {acc[i][0], acc[i][1], acc[i][2], acc[i][3]};
        float4 r1 = {acc[i][4], acc[i][5], acc[i][6], acc[i][7]};
        *(float4*)&C[(size_t)(bm + tm + i) * N + bn + tn]     = r0;
        *(float4*)&C[(size_t)(bm + tm + i) * N + bn + tn + 4] = r1;
    }
}

// ---------------- small GEMM: g_ba[2048,64] = A[2048,2048] * W[2048,64] -----
__global__ __launch_bounds__(256) void gemm_ba_kernel(const float* __restrict__ A,
                                                      const float* __restrict__ W)
{
    __shared__ float As[32][64];
    int tid = threadIdx.x;
    int col = tid & 63;
    int rg  = tid >> 6;                 // 0..3, each handles 8 rows
    int rowblk = blockIdx.x * 32;

    float acc[8];
#pragma unroll
    for (int r = 0; r < 8; r++) acc[r] = 0.f;

    for (int k0 = 0; k0 < H_; k0 += 64) {
        __syncthreads();
#pragma unroll
        for (int it = 0; it < 8; it++) {
            int idx = it * 256 + tid;
            int rr = idx >> 6, kk = idx & 63;
            As[rr][kk] = A[(size_t)(rowblk + rr) * H_ + k0 + kk];
        }
        __syncthreads();
        for (int kk = 0; kk < 64; kk++) {
            float w = W[(size_t)(k0 + kk) * 64 + col];
#pragma unroll
            for (int rr = 0; rr < 8; rr++) acc[rr] += As[rg * 8 + rr][kk] * w;
        }
    }
#pragma unroll
    for (int rr = 0; rr < 8; rr++)
        g_ba[(size_t)(rowblk + rg * 8 + rr) * 64 + col] = acc[rr];
}

__device__ __forceinline__ float silu_f(float x) { return x / (1.f + expf(-x)); }

// ---------------- q/k depthwise conv4 + silu + l2norm ----------------------
// grid (S, 16, B), 128 threads
__global__ __launch_bounds__(128) void qk_conv_norm_kernel(const float* __restrict__ conv_w)
{
    int s = blockIdx.x, h = blockIdx.y, b = blockIdx.z;
    int d = threadIdx.x;
    int colq = h * 768 + d;
    int colk = colq + 128;
    int cq = h * 128 + d;          // conv channel for q
    int ck = 2048 + h * 128 + d;   // conv channel for k

    float xq = 0.f, xk = 0.f;
#pragma unroll
    for (int j = 0; j < 4; j++) {
        int ss = s - 3 + j;
        if (ss >= 0) {
            const float* row = g_qkvz + (size_t)(b * S_ + ss) * QKVZW;
            xq += conv_w[cq * 4 + j] * row[colq];
            xk += conv_w[ck * 4 + j] * row[colk];
        }
    }
    xq = silu_f(xq);
    xk = silu_f(xk);

    float sq2 = xq * xq, sk2 = xk * xk;
#pragma unroll
    for (int o = 16; o > 0; o >>= 1) {
        sq2 += __shfl_xor_sync(0xffffffffu, sq2, o);
        sk2 += __shfl_xor_sync(0xffffffffu, sk2, o);
    }
    __shared__ float bufq[4], bufk[4];
    if ((d & 31) == 0) { bufq[d >> 5] = sq2; bufk[d >> 5] = sk2; }
    __syncthreads();
    float sumq = bufq[0] + bufq[1] + bufq[2] + bufq[3];
    float sumk = bufk[0] + bufk[1] + bufk[2] + bufk[3];
    float rq = rsqrtf(sumq + 1e-6f) * 0.08838834764831845f;  // * DK^-0.5
    float rk = rsqrtf(sumk + 1e-6f);
    size_t base = ((size_t)(b * NK_ + h) * S_ + s) * DK_ + d;
    g_q[base] = xq * rq;
    g_k[base] = xk * rk;
}

// ---------------- v conv4 + silu, beta / exp(g) gates ----------------------
// grid (S, 32, B), 128 threads
__global__ __launch_bounds__(128) void v_conv_gate_kernel(const float* __restrict__ conv_w,
                                                          const float* __restrict__ dt_bias,
                                                          const float* __restrict__ A_log)
{
    int s = blockIdx.x, vh = blockIdx.y, b = blockIdx.z;
    int d = threadIdx.x;
    int kh = vh >> 1, sub = vh & 1;
    int col = kh * 768 + 256 + sub * 128 + d;
    int cc  = 4096 + vh * 128 + d;

    float x = 0.f;
#pragma unroll
    for (int j = 0; j < 4; j++) {
        int ss = s - 3 + j;
        if (ss >= 0)
            x += conv_w[cc * 4 + j] * g_qkvz[(size_t)(b * S_ + ss) * QKVZW + col];
    }
    g_v[((size_t)(b * NV_ + vh) * S_ + s) * DV_ + d] = silu_f(x);

    if (d == 0) {
        const float* barow = g_ba + (size_t)(b * S_ + s) * 64;
        float bb = barow[kh * 4 + sub];
        float aa = barow[kh * 4 + 2 + sub];
        float beta = 1.f / (1.f + expf(-bb));
        float xx = aa + dt_bias[vh];
        float sp = (xx > 20.f) ? xx : log1pf(expf(xx));
        float g  = -expf(A_log[vh]) * sp;
        g_beta[(size_t)(b * NV_ + vh) * S_ + s] = beta;
        g_eg  [(size_t)(b * NV_ + vh) * S_ + s] = expf(g);
    }
}

// ---------------- gated delta-rule scan ------------------------------------
// grid = B*32*4 = 256 CTAs (dv sliced by 32), 128 threads = 4 warps.
// Thread (warp,lane): column c = warp*8 + lane>>2 (within slice), r = lane&3
// owns dk rows [r*32, r*32+32). State in registers (32 f32). Reductions over
// the 4-lane quad via shfl_xor — no barriers in the step loop.
#define SCAN_T 32
__global__ __launch_bounds__(128) void scan_kernel()
{
    int flat = blockIdx.x;
    int sl = flat & 3;
    int vh = (flat >> 2) & 31;
    int b  = flat >> 7;
    int kh = vh >> 1;

    int tid = threadIdx.x;
    int warp = tid >> 5, lane = tid & 31;
    int c = warp * 8 + (lane >> 2);   // 0..31
    int r = lane & 3;
    int dkb = r * 32;

    __shared__ float sk[SCAN_T][128];
    __shared__ float sq[SCAN_T][128];
    __shared__ float sv[SCAN_T][32];
    __shared__ float seg[SCAN_T], sb[SCAN_T];

    const float* kbase  = g_k + (size_t)(b * NK_ + kh) * S_ * DK_;
    const float* qbase  = g_q + (size_t)(b * NK_ + kh) * S_ * DK_;
    const float* vbase  = g_v + (size_t)(b * NV_ + vh) * S_ * DV_ + sl * 32;
    const float* egbase = g_eg   + (size_t)(b * NV_ + vh) * S_;
    const float* btbase = g_beta + (size_t)(b * NV_ + vh) * S_;
    float* obase = g_o + (size_t)(b * NV_ + vh) * S_ * DV_ + sl * 32;

    float st[32];
#pragma unroll
    for (int i = 0; i < 32; i++) st[i] = 0.f;

    for (int s0 = 0; s0 < S_; s0 += SCAN_T) {
#pragma unroll
        for (int it = 0; it < 8; it++) {
            int idx = it * 128 + tid;          // float4 index, 1024 total
            int t = idx >> 5, d4 = (idx & 31) << 2;
            *(float4*)&sk[t][d4] = *(const float4*)&kbase[(size_t)(s0 + t) * DK_ + d4];
            *(float4*)&sq[t][d4] = *(const float4*)&qbase[(size_t)(s0 + t) * DK_ + d4];
        }
#pragma unroll
        for (int it = 0; it < 2; it++) {
            int idx = it * 128 + tid;          // 256 float4
            int t = idx >> 3, d4 = (idx & 7) << 2;
            *(float4*)&sv[t][d4] = *(const float4*)&vbase[(size_t)(s0 + t) * DV_ + d4];
        }
        if (tid < SCAN_T) { seg[tid] = egbase[s0 + tid]; sb[tid] = btbase[s0 + tid]; }
        __syncthreads();

        for (int t = 0; t < SCAN_T; t++) {
            float eg = seg[t], bt = sb[t], vt = sv[t][c];
            float kreg[32];
#pragma unroll
            for (int i4 = 0; i4 < 8; i4++) {
                float4 kk = *(float4*)&sk[t][dkb + i4 * 4];
                kreg[i4 * 4 + 0] = kk.x; kreg[i4 * 4 + 1] = kk.y;
                kreg[i4 * 4 + 2] = kk.z; kreg[i4 * 4 + 3] = kk.w;
            }
            float kv = 0.f;
#pragma unroll
            for (int i = 0; i < 32; i++) { st[i] *= eg; kv += st[i] * kreg[i]; }
            kv += __shfl_xor_sync(0xffffffffu, kv, 1);
            kv += __shfl_xor_sync(0xffffffffu, kv, 2);
            float delta = (vt - kv) * bt;
            float o = 0.f;
#pragma unroll
            for (int i4 = 0; i4 < 8; i4++) {
                float4 qq = *(float4*)&sq[t][dkb + i4 * 4];
                st[i4 * 4 + 0] += kreg[i4 * 4 + 0] * delta; o += qq.x * st[i4 * 4 + 0];
                st[i4 * 4 + 1] += kreg[i4 * 4 + 1] * delta; o += qq.y * st[i4 * 4 + 1];
                st[i4 * 4 + 2] += kreg[i4 * 4 + 2] * delta; o += qq.z * st[i4 * 4 + 2];
                st[i4 * 4 + 3] += kreg[i4 * 4 + 3] * delta; o += qq.w * st[i4 * 4 + 3];
            }
            o += __shfl_xor_sync(0xffffffffu, o, 1);
            o += __shfl_xor_sync(0xffffffffu, o, 2);
            if (r == 0) obase[(size_t)(s0 + t) * DV_ + c] = o;
        }
        __syncthreads();
    }
}

// ---------------- gated RMSNorm --------------------------------------------
// grid (S, 32, B), 128 threads
__global__ __launch_bounds__(128) void rmsnorm_kernel(const float* __restrict__ norm_w)
{
    int s = blockIdx.x, vh = blockIdx.y, b = blockIdx.z;
    int d = threadIdx.x;
    float x = g_o[((size_t)(b * NV_ + vh) * S_ + s) * DV_ + d];
    float z = g_qkvz[(size_t)(b * S_ + s) * QKVZW + (vh >> 1) * 768 + 512 + (vh & 1) * 128 + d];
    float xg = x * silu_f(z);

    float ss = xg * xg;
#pragma unroll
    for (int o = 16; o > 0; o >>= 1) ss += __shfl_xor_sync(0xffffffffu, ss, o);
    __shared__ float buf[4];
    if ((d & 31) == 0) buf[d >> 5] = ss;
    __syncthreads();
    float sum = buf[0] + buf[1] + buf[2] + buf[3];
    float y = xg * rsqrtf(sum * (1.f / 128.f) + 1e-6f) * norm_w[d];
    g_y[(size_t)(b * S_ + s) * VDIM_ + vh * 128 + d] = y;
}

// ---------------- launch ----------------------------------------------------
extern "C" void kernel_launch(void* const* d_in, const int* in_sizes, int n_in,
                              void* d_out, int out_size)
{
    const float* hidden  = (const float*)d_in[0];
    const float* w_qkvz  = (const float*)d_in[1];
    const float* w_ba    = (const float*)d_in[2];
    const float* conv_w  = (const float*)d_in[3];
    const float* dt_bias = (const float*)d_in[4];
    const float* A_log   = (const float*)d_in[5];
    const float* norm_w  = (const float*)d_in[6];
    const float* w_out   = (const float*)d_in[7];
    float* out = (float*)d_out;

    float *qkvz_p = nullptr, *y_p = nullptr;
    cudaGetSymbolAddress((void**)&qkvz_p, g_qkvz);
    cudaGetSymbolAddress((void**)&y_p, g_y);

    // 1) big projection + ba projection
    sgemm128<<<dim3(QKVZW / 128, TOK_ / 128), 256>>>(hidden, w_qkvz, qkvz_p, TOK_, QKVZW, H_);
    gemm_ba_kernel<<<TOK_ / 32, 256>>>(hidden, w_ba);

    // 2) conv + activations + norms + gates
    qk_conv_norm_kernel<<<dim3(S_, NK_, B_), 128>>>(conv_w);
    v_conv_gate_kernel<<<dim3(S_, NV_, B_), 128>>>(conv_w, dt_bias, A_log);

    // 3) gated delta-rule recurrence
    scan_kernel<<<B_ * NV_ * 4, 128>>>();

    // 4) gated RMSNorm
    rmsnorm_kernel<<<dim3(S_, NV_, B_), 128>>>(norm_w);

    // 5) output projection
    sgemm128<<<dim3(H_ / 128, TOK_ / 128), 256>>>(y_p, w_out, out, TOK_, H_, VDIM_);
}

// round 3
// speedup vs baseline: 1.6080x; 1.6080x over previous
#include <cuda_runtime.h>
#include <cuda_bf16.h>
#include <math.h>
#include <cstdint>

// ---------------- problem constants ----------------
#define B_    2
#define S_    1024
#define H_    2048
#define NK_   16
#define NV_   32
#define DK_   128
#define DV_   128
#define QKVZW 12288     // 2*KDIM + 2*VDIM
#define KDIM_ 2048
#define VDIM_ 4096
#define TOK_  (B_*S_)   // 2048

// ---------------- scratch (device globals; no cudaMalloc allowed) ----------
__device__ float g_qkvz[(size_t)TOK_ * QKVZW];         // [B*S, 12288]
__device__ float g_ba  [(size_t)TOK_ * 64];            // [B*S, 64]
__device__ float g_q   [(size_t)B_ * NK_ * S_ * DK_];
__device__ float g_k   [(size_t)B_ * NK_ * S_ * DK_];
__device__ float g_v   [(size_t)B_ * NV_ * S_ * DV_];
__device__ float g_eg  [(size_t)B_ * NV_ * S_];
__device__ float g_beta[(size_t)B_ * NV_ * S_];
__device__ float g_o   [(size_t)B_ * NV_ * S_ * DV_];

// bf16 split operands for tensor GEMMs
__device__ __nv_bfloat16 g_hid_hi[(size_t)TOK_ * H_];
__device__ __nv_bfloat16 g_hid_lo[(size_t)TOK_ * H_];
__device__ __nv_bfloat16 g_wqkvz_hi[(size_t)QKVZW * H_];   // transposed [N=12288, K=2048]
__device__ __nv_bfloat16 g_wqkvz_lo[(size_t)QKVZW * H_];
__device__ __nv_bfloat16 g_wout_hi[(size_t)H_ * VDIM_];    // transposed [N=2048, K=4096]
__device__ __nv_bfloat16 g_wout_lo[(size_t)H_ * VDIM_];
__device__ __nv_bfloat16 g_y_hi[(size_t)TOK_ * VDIM_];     // [M=2048, K=4096]
__device__ __nv_bfloat16 g_y_lo[(size_t)TOK_ * VDIM_];

// ---------------- split kernels ---------------------------------------------
__global__ __launch_bounds__(256) void split_kernel(const float* __restrict__ src,
                                                    __nv_bfloat16* __restrict__ hi,
                                                    __nv_bfloat16* __restrict__ lo, int n4)
{
    int i = blockIdx.x * 256 + threadIdx.x;
    if (i >= n4) return;
    float4 x = ((const float4*)src)[i];
    __nv_bfloat16 h0 = __float2bfloat16(x.x), h1 = __float2bfloat16(x.y);
    __nv_bfloat16 h2 = __float2bfloat16(x.z), h3 = __float2bfloat16(x.w);
    __nv_bfloat162 hh0{h0, h1}, hh1{h2, h3};
    __nv_bfloat162 ll0{__float2bfloat16(x.x - __bfloat162float(h0)),
                       __float2bfloat16(x.y - __bfloat162float(h1))};
    __nv_bfloat162 ll1{__float2bfloat16(x.z - __bfloat162float(h2)),
                       __float2bfloat16(x.w - __bfloat162float(h3))};
    ((__nv_bfloat162*)hi)[i * 2]     = hh0;
    ((__nv_bfloat162*)hi)[i * 2 + 1] = hh1;
    ((__nv_bfloat162*)lo)[i * 2]     = ll0;
    ((__nv_bfloat162*)lo)[i * 2 + 1] = ll1;
}

// src [K,N] row-major -> hi/lo [N,K] (transposed), bf16 split
__global__ __launch_bounds__(256) void transpose_split_kernel(const float* __restrict__ src,
                                                              __nv_bfloat16* __restrict__ hi,
                                                              __nv_bfloat16* __restrict__ lo,
                                                              int K, int N)
{
    __shared__ float tile[32][33];
    int nb = blockIdx.x * 32, kb = blockIdx.y * 32;
    int tx = threadIdx.x & 31, ty = threadIdx.x >> 5;   // 32 x 8
#pragma unroll
    for (int j = 0; j < 32; j += 8)
        tile[ty + j][tx] = src[(size_t)(kb + ty + j) * N + nb + tx];
    __syncthreads();
#pragma unroll
    for (int j = 0; j < 32; j += 8) {
        float x = tile[tx][ty + j];                     // src[kb+tx][nb+ty+j]
        __nv_bfloat16 h = __float2bfloat16(x);
        size_t oidx = (size_t)(nb + ty + j) * K + kb + tx;
        hi[oidx] = h;
        lo[oidx] = __float2bfloat16(x - __bfloat162float(h));
    }
}

// ---------------- HMMA split-bf16 GEMM ---------------------------------------
// C[M,N] = A[M,K] * B[N,K]^T; A,B given as hi+lo bf16 (K-major).
// CTA tile 128x128, BK=32, 256 threads (8 warps of 32x64), cp.async double buffer.
#define BKg   32
#define PADK  40          // padded row length (elements)
#define TILEB (128 * PADK * 2)  // 10240 bytes per operand tile

#define LDSM4(r0, r1, r2, r3, addr) \
    asm volatile("ldmatrix.sync.aligned.m8n8.x4.shared.b16 {%0,%1,%2,%3}, [%4];" \
        : "=r"(r0), "=r"(r1), "=r"(r2), "=r"(r3) : "r"(addr))

#define MMA16816(d, a, b) \
    asm volatile("mma.sync.aligned.m16n8k16.row.col.f32.bf16.bf16.f32 " \
        "{%0,%1,%2,%3}, {%4,%5,%6,%7}, {%8,%9}, {%0,%1,%2,%3};" \
        : "+f"((d)[0]), "+f"((d)[1]), "+f"((d)[2]), "+f"((d)[3]) \
        : "r"((a)[0]), "r"((a)[1]), "r"((a)[2]), "r"((a)[3]), "r"((b)[0]), "r"((b)[1]))

#define CP_ASYNC16(saddr, gptr) \
    asm volatile("cp.async.cg.shared.global [%0], [%1], 16;" :: "r"(saddr), "l"(gptr))
#define CP_COMMIT() asm volatile("cp.async.commit_group;" ::: "memory")
#define CP_WAIT1()  asm volatile("cp.async.wait_group 1;" ::: "memory")

__device__ __forceinline__ uint32_t smem_u32_of(const void* p) {
    uint32_t a;
    asm("{ .reg .u64 t; cvta.to.shared.u64 t, %1; cvt.u32.u64 %0, t; }" : "=r"(a) : "l"(p));
    return a;
}

__global__ __launch_bounds__(256) void gemm_bf16s(
    const __nv_bfloat16* __restrict__ Ah, const __nv_bfloat16* __restrict__ Al,
    const __nv_bfloat16* __restrict__ Bh, const __nv_bfloat16* __restrict__ Bl,
    float* __restrict__ C, int M, int N, int K)
{
    extern __shared__ char smem[];
    uint32_t sbase = smem_u32_of(smem);

    int tid = threadIdx.x;
    int wid = tid >> 5, lane = tid & 31;
    int m0 = blockIdx.x * 128;
    int n0 = blockIdx.y * 128;
    int m_w = (wid >> 1) * 32;       // warp M offset (0,32,64,96)
    int n_w = (wid & 1) * 64;        // warp N offset (0,64)

    float acc[2][8][4];
#pragma unroll
    for (int i = 0; i < 2; i++)
#pragma unroll
        for (int j = 0; j < 8; j++)
#pragma unroll
            for (int l = 0; l < 4; l++) acc[i][j][l] = 0.f;

    const int NC = K / BKg;

    // per-lane ldmatrix address components
    int aRow = lane & 15;
    int aColH = (lane >> 4) << 3;            // 0 or 8
    int bRow = (lane & 7) | ((lane & 16) >> 1);  // (lane&7) + (lane&16 ? 8 : 0)
    int bColH = lane & 8;                    // 0 or 8

    // stage loader
    auto load_chunk = [&](int kc, int bsel) {
        int kbase = kc * BKg;
        uint32_t sst = sbase + bsel * (4 * TILEB);
#pragma unroll
        for (int i = 0; i < 8; i++) {
            int idx = i * 256 + tid;         // 0..2047
            int t = idx >> 9;                // 0:Ah 1:Al 2:Bh 3:Bl
            int w = idx & 511;
            int r = w >> 2, c8 = (w & 3) << 3;
            const __nv_bfloat16* src = (t == 0) ? Ah : (t == 1) ? Al : (t == 2) ? Bh : Bl;
            int row = (t < 2) ? (m0 + r) : (n0 + r);
            const __nv_bfloat16* g = src + (size_t)row * K + kbase + c8;
            uint32_t sa = sst + t * TILEB + (uint32_t)(r * PADK + c8) * 2;
            CP_ASYNC16(sa, g);
        }
    };

    load_chunk(0, 0); CP_COMMIT();
    load_chunk(1, 1); CP_COMMIT();

    for (int kc = 0; kc < NC; kc++) {
        CP_WAIT1();
        __syncthreads();

        int bsel = kc & 1;
        uint32_t sst = sbase + bsel * (4 * TILEB);
        uint32_t sAh = sst;
        uint32_t sAl = sst + TILEB;
        uint32_t sBh = sst + 2 * TILEB;
        uint32_t sBl = sst + 3 * TILEB;

#pragma unroll
        for (int ks = 0; ks < 2; ks++) {
            int k0 = ks * 16;
            uint32_t aH[2][4], aL[2][4], bH[8][2], bL[8][2];
#pragma unroll
            for (int mt = 0; mt < 2; mt++) {
                uint32_t off = (uint32_t)((m_w + mt * 16 + aRow) * PADK + k0 + aColH) * 2;
                LDSM4(aH[mt][0], aH[mt][1], aH[mt][2], aH[mt][3], sAh + off);
                LDSM4(aL[mt][0], aL[mt][1], aL[mt][2], aL[mt][3], sAl + off);
            }
#pragma unroll
            for (int g2 = 0; g2 < 4; g2++) {
                uint32_t off = (uint32_t)((n_w + g2 * 16 + bRow) * PADK + k0 + bColH) * 2;
                LDSM4(bH[g2 * 2][0], bH[g2 * 2][1], bH[g2 * 2 + 1][0], bH[g2 * 2 + 1][1], sBh + off);
                LDSM4(bL[g2 * 2][0], bL[g2 * 2][1], bL[g2 * 2 + 1][0], bL[g2 * 2 + 1][1], sBl + off);
            }
#pragma unroll
            for (int mt = 0; mt < 2; mt++)
#pragma unroll
                for (int nt = 0; nt < 8; nt++) MMA16816(acc[mt][nt], aH[mt], bH[nt]);
#pragma unroll
            for (int mt = 0; mt < 2; mt++)
#pragma unroll
                for (int nt = 0; nt < 8; nt++) MMA16816(acc[mt][nt], aH[mt], bL[nt]);
#pragma unroll
            for (int mt = 0; mt < 2; mt++)
#pragma unroll
                for (int nt = 0; nt < 8; nt++) MMA16816(acc[mt][nt], aL[mt], bH[nt]);
        }

        __syncthreads();
        if (kc + 2 < NC) load_chunk(kc + 2, bsel);
        CP_COMMIT();   // empty groups at tail keep wait_group invariant exact
    }

    // epilogue: write f32 C
    int cr = lane >> 2;            // 0..7
    int cc = (lane & 3) * 2;       // 0,2,4,6
#pragma unroll
    for (int mt = 0; mt < 2; mt++) {
#pragma unroll
        for (int nt = 0; nt < 8; nt++) {
            int row = m0 + m_w + mt * 16 + cr;
            int col = n0 + n_w + nt * 8 + cc;
            float2 v0 = {acc[mt][nt][0], acc[mt][nt][1]};
            float2 v1 = {acc[mt][nt][2], acc[mt][nt][3]};
            *(float2*)&C[(size_t)row * N + col]       = v0;
            *(float2*)&C[(size_t)(row + 8) * N + col] = v1;
        }
    }
}
#define GSMEM_BYTES (8 * TILEB)   // 81920

// ---------------- small GEMM: g_ba[2048,64] = A[2048,2048] * W[2048,64] -----
__global__ __launch_bounds__(256) void gemm_ba_kernel(const float* __restrict__ A,
                                                      const float* __restrict__ W)
{
    __shared__ float As[32][64];
    int tid = threadIdx.x;
    int col = tid & 63;
    int rg  = tid >> 6;
    int rowblk = blockIdx.x * 32;

    float acc[8];
#pragma unroll
    for (int r = 0; r < 8; r++) acc[r] = 0.f;

    for (int k0 = 0; k0 < H_; k0 += 64) {
        __syncthreads();
#pragma unroll
        for (int it = 0; it < 8; it++) {
            int idx = it * 256 + tid;
            int rr = idx >> 6, kk = idx & 63;
            As[rr][kk] = A[(size_t)(rowblk + rr) * H_ + k0 + kk];
        }
        __syncthreads();
        for (int kk = 0; kk < 64; kk++) {
            float w = W[(size_t)(k0 + kk) * 64 + col];
#pragma unroll
            for (int rr = 0; rr < 8; rr++) acc[rr] += As[rg * 8 + rr][kk] * w;
        }
    }
#pragma unroll
    for (int rr = 0; rr < 8; rr++)
        g_ba[(size_t)(rowblk + rg * 8 + rr) * 64 + col] = acc[rr];
}

__device__ __forceinline__ float silu_f(float x) { return x / (1.f + expf(-x)); }

// ---------------- q/k depthwise conv4 + silu + l2norm ----------------------
__global__ __launch_bounds__(128) void qk_conv_norm_kernel(const float* __restrict__ conv_w)
{
    int s = blockIdx.x, h = blockIdx.y, b = blockIdx.z;
    int d = threadIdx.x;
    int colq = h * 768 + d;
    int colk = colq + 128;
    int cq = h * 128 + d;
    int ck = 2048 + h * 128 + d;

    float xq = 0.f, xk = 0.f;
#pragma unroll
    for (int j = 0; j < 4; j++) {
        int ss = s - 3 + j;
        if (ss >= 0) {
            const float* row = g_qkvz + (size_t)(b * S_ + ss) * QKVZW;
            xq += conv_w[cq * 4 + j] * row[colq];
            xk += conv_w[ck * 4 + j] * row[colk];
        }
    }
    xq = silu_f(xq);
    xk = silu_f(xk);

    float sq2 = xq * xq, sk2 = xk * xk;
#pragma unroll
    for (int o = 16; o > 0; o >>= 1) {
        sq2 += __shfl_xor_sync(0xffffffffu, sq2, o);
        sk2 += __shfl_xor_sync(0xffffffffu, sk2, o);
    }
    __shared__ float bufq[4], bufk[4];
    if ((d & 31) == 0) { bufq[d >> 5] = sq2; bufk[d >> 5] = sk2; }
    __syncthreads();
    float sumq = bufq[0] + bufq[1] + bufq[2] + bufq[3];
    float sumk = bufk[0] + bufk[1] + bufk[2] + bufk[3];
    float rq = rsqrtf(sumq + 1e-6f) * 0.08838834764831845f;
    float rk = rsqrtf(sumk + 1e-6f);
    size_t base = ((size_t)(b * NK_ + h) * S_ + s) * DK_ + d;
    g_q[base] = xq * rq;
    g_k[base] = xk * rk;
}

// ---------------- v conv4 + silu, beta / exp(g) gates ----------------------
__global__ __launch_bounds__(128) void v_conv_gate_kernel(const float* __restrict__ conv_w,
                                                          const float* __restrict__ dt_bias,
                                                          const float* __restrict__ A_log)
{
    int s = blockIdx.x, vh = blockIdx.y, b = blockIdx.z;
    int d = threadIdx.x;
    int kh = vh >> 1, sub = vh & 1;
    int col = kh * 768 + 256 + sub * 128 + d;
    int cc  = 4096 + vh * 128 + d;

    float x = 0.f;
#pragma unroll
    for (int j = 0; j < 4; j++) {
        int ss = s - 3 + j;
        if (ss >= 0)
            x += conv_w[cc * 4 + j] * g_qkvz[(size_t)(b * S_ + ss) * QKVZW + col];
    }
    g_v[((size_t)(b * NV_ + vh) * S_ + s) * DV_ + d] = silu_f(x);

    if (d == 0) {
        const float* barow = g_ba + (size_t)(b * S_ + s) * 64;
        float bb = barow[kh * 4 + sub];
        float aa = barow[kh * 4 + 2 + sub];
        float beta = 1.f / (1.f + expf(-bb));
        float xx = aa + dt_bias[vh];
        float sp = (xx > 20.f) ? xx : log1pf(expf(xx));
        float g  = -expf(A_log[vh]) * sp;
        g_beta[(size_t)(b * NV_ + vh) * S_ + s] = beta;
        g_eg  [(size_t)(b * NV_ + vh) * S_ + s] = expf(g);
    }
}

// ---------------- gated delta-rule scan ------------------------------------
#define SCAN_T 32
__global__ __launch_bounds__(128) void scan_kernel()
{
    int flat = blockIdx.x;
    int sl = flat & 3;
    int vh = (flat >> 2) & 31;
    int b  = flat >> 7;
    int kh = vh >> 1;

    int tid = threadIdx.x;
    int warp = tid >> 5, lane = tid & 31;
    int c = warp * 8 + (lane >> 2);
    int r = lane & 3;
    int dkb = r * 32;

    __shared__ float sk[SCAN_T][128];
    __shared__ float sq[SCAN_T][128];
    __shared__ float sv[SCAN_T][32];
    __shared__ float seg[SCAN_T], sb[SCAN_T];

    const float* kbase  = g_k + (size_t)(b * NK_ + kh) * S_ * DK_;
    const float* qbase  = g_q + (size_t)(b * NK_ + kh) * S_ * DK_;
    const float* vbase  = g_v + (size_t)(b * NV_ + vh) * S_ * DV_ + sl * 32;
    const float* egbase = g_eg   + (size_t)(b * NV_ + vh) * S_;
    const float* btbase = g_beta + (size_t)(b * NV_ + vh) * S_;
    float* obase = g_o + (size_t)(b * NV_ + vh) * S_ * DV_ + sl * 32;

    float st[32];
#pragma unroll
    for (int i = 0; i < 32; i++) st[i] = 0.f;

    for (int s0 = 0; s0 < S_; s0 += SCAN_T) {
#pragma unroll
        for (int it = 0; it < 8; it++) {
            int idx = it * 128 + tid;
            int t = idx >> 5, d4 = (idx & 31) << 2;
            *(float4*)&sk[t][d4] = *(const float4*)&kbase[(size_t)(s0 + t) * DK_ + d4];
            *(float4*)&sq[t][d4] = *(const float4*)&qbase[(size_t)(s0 + t) * DK_ + d4];
        }
#pragma unroll
        for (int it = 0; it < 2; it++) {
            int idx = it * 128 + tid;
            int t = idx >> 3, d4 = (idx & 7) << 2;
            *(float4*)&sv[t][d4] = *(const float4*)&vbase[(size_t)(s0 + t) * DV_ + d4];
        }
        if (tid < SCAN_T) { seg[tid] = egbase[s0 + tid]; sb[tid] = btbase[s0 + tid]; }
        __syncthreads();

        for (int t = 0; t < SCAN_T; t++) {
            float eg = seg[t], bt = sb[t], vt = sv[t][c];
            float kreg[32];
#pragma unroll
            for (int i4 = 0; i4 < 8; i4++) {
                float4 kk = *(float4*)&sk[t][dkb + i4 * 4];
                kreg[i4 * 4 + 0] = kk.x; kreg[i4 * 4 + 1] = kk.y;
                kreg[i4 * 4 + 2] = kk.z; kreg[i4 * 4 + 3] = kk.w;
            }
            float kv = 0.f;
#pragma unroll
            for (int i = 0; i < 32; i++) { st[i] *= eg; kv += st[i] * kreg[i]; }
            kv += __shfl_xor_sync(0xffffffffu, kv, 1);
            kv += __shfl_xor_sync(0xffffffffu, kv, 2);
            float delta = (vt - kv) * bt;
            float o = 0.f;
#pragma unroll
            for (int i4 = 0; i4 < 8; i4++) {
                float4 qq = *(float4*)&sq[t][dkb + i4 * 4];
                st[i4 * 4 + 0] += kreg[i4 * 4 + 0] * delta; o += qq.x * st[i4 * 4 + 0];
                st[i4 * 4 + 1] += kreg[i4 * 4 + 1] * delta; o += qq.y * st[i4 * 4 + 1];
                st[i4 * 4 + 2] += kreg[i4 * 4 + 2] * delta; o += qq.z * st[i4 * 4 + 2];
                st[i4 * 4 + 3] += kreg[i4 * 4 + 3] * delta; o += qq.w * st[i4 * 4 + 3];
            }
            o += __shfl_xor_sync(0xffffffffu, o, 1);
            o += __shfl_xor_sync(0xffffffffu, o, 2);
            if (r == 0) obase[(size_t)(s0 + t) * DV_ + c] = o;
        }
        __syncthreads();
    }
}

// ---------------- gated RMSNorm (emits split-bf16 y) ------------------------
__global__ __launch_bounds__(128) void rmsnorm_kernel(const float* __restrict__ norm_w)
{
    int s = blockIdx.x, vh = blockIdx.y, b = blockIdx.z;
    int d = threadIdx.x;
    float x = g_o[((size_t)(b * NV_ + vh) * S_ + s) * DV_ + d];
    float z = g_qkvz[(size_t)(b * S_ + s) * QKVZW + (vh >> 1) * 768 + 512 + (vh & 1) * 128 + d];
    float xg = x * silu_f(z);

    float ss = xg * xg;
#pragma unroll
    for (int o = 16; o > 0; o >>= 1) ss += __shfl_xor_sync(0xffffffffu, ss, o);
    __shared__ float buf[4];
    if ((d & 31) == 0) buf[d >> 5] = ss;
    __syncthreads();
    float sum = buf[0] + buf[1] + buf[2] + buf[3];
    float y = xg * rsqrtf(sum * (1.f / 128.f) + 1e-6f) * norm_w[d];
    size_t oidx = (size_t)(b * S_ + s) * VDIM_ + vh * 128 + d;
    __nv_bfloat16 h = __float2bfloat16(y);
    g_y_hi[oidx] = h;
    g_y_lo[oidx] = __float2bfloat16(y - __bfloat162float(h));
}

// ---------------- launch ----------------------------------------------------
extern "C" void kernel_launch(void* const* d_in, const int* in_sizes, int n_in,
                              void* d_out, int out_size)
{
    const float* hidden  = (const float*)d_in[0];
    const float* w_qkvz  = (const float*)d_in[1];
    const float* w_ba    = (const float*)d_in[2];
    const float* conv_w  = (const float*)d_in[3];
    const float* dt_bias = (const float*)d_in[4];
    const float* A_log   = (const float*)d_in[5];
    const float* norm_w  = (const float*)d_in[6];
    const float* w_out   = (const float*)d_in[7];
    float* out = (float*)d_out;

    float *qkvz_p = nullptr;
    cudaGetSymbolAddress((void**)&qkvz_p, g_qkvz);
    __nv_bfloat16 *hid_hi, *hid_lo, *wq_hi, *wq_lo, *wo_hi, *wo_lo, *y_hi, *y_lo;
    cudaGetSymbolAddress((void**)&hid_hi, g_hid_hi);
    cudaGetSymbolAddress((void**)&hid_lo, g_hid_lo);
    cudaGetSymbolAddress((void**)&wq_hi, g_wqkvz_hi);
    cudaGetSymbolAddress((void**)&wq_lo, g_wqkvz_lo);
    cudaGetSymbolAddress((void**)&wo_hi, g_wout_hi);
    cudaGetSymbolAddress((void**)&wo_lo, g_wout_lo);
    cudaGetSymbolAddress((void**)&y_hi, g_y_hi);
    cudaGetSymbolAddress((void**)&y_lo, g_y_lo);

    cudaFuncSetAttribute(gemm_bf16s, cudaFuncAttributeMaxDynamicSharedMemorySize, GSMEM_BYTES);

    // 0) precision splits (+ weight transposes to [N,K])
    split_kernel<<<(TOK_ * H_ / 4 + 255) / 256, 256>>>(hidden, hid_hi, hid_lo, TOK_ * H_ / 4);
    transpose_split_kernel<<<dim3(QKVZW / 32, H_ / 32), 256>>>(w_qkvz, wq_hi, wq_lo, H_, QKVZW);
    transpose_split_kernel<<<dim3(H_ / 32, VDIM_ / 32), 256>>>(w_out, wo_hi, wo_lo, VDIM_, H_);

    // 1) projections
    gemm_bf16s<<<dim3(TOK_ / 128, QKVZW / 128), 256, GSMEM_BYTES>>>(
        hid_hi, hid_lo, wq_hi, wq_lo, qkvz_p, TOK_, QKVZW, H_);
    gemm_ba_kernel<<<TOK_ / 32, 256>>>(hidden, w_ba);

    // 2) conv + activations + norms + gates
    qk_conv_norm_kernel<<<dim3(S_, NK_, B_), 128>>>(conv_w);
    v_conv_gate_kernel<<<dim3(S_, NV_, B_), 128>>>(conv_w, dt_bias, A_log);

    // 3) gated delta-rule recurrence
    scan_kernel<<<B_ * NV_ * 4, 128>>>();

    // 4) gated RMSNorm -> split-bf16 y
    rmsnorm_kernel<<<dim3(S_, NV_, B_), 128>>>(norm_w);

    // 5) output projection
    gemm_bf16s<<<dim3(TOK_ / 128, H_ / 128), 256, GSMEM_BYTES>>>(
        y_hi, y_lo, wo_hi, wo_lo, out, TOK_, H_, VDIM_);
}

// round 4
// speedup vs baseline: 1.7685x; 1.0998x over previous
#include <cuda_runtime.h>
#include <cuda_bf16.h>
#include <math.h>
#include <cstdint>

// ---------------- problem constants ----------------
#define B_    2
#define S_    1024
#define H_    2048
#define NK_   16
#define NV_   32
#define DK_   128
#define DV_   128
#define QKVZW 12288     // 2*KDIM + 2*VDIM
#define KDIM_ 2048
#define VDIM_ 4096
#define TOK_  (B_*S_)   // 2048

// ---------------- scratch (device globals; no cudaMalloc allowed) ----------
__device__ float g_qkvz[(size_t)TOK_ * QKVZW];         // [B*S, 12288]
__device__ float g_ba  [(size_t)TOK_ * 64];            // [B*S, 64]
__device__ float g_q   [(size_t)B_ * NK_ * S_ * DK_];
__device__ float g_k   [(size_t)B_ * NK_ * S_ * DK_];
__device__ float g_v   [(size_t)B_ * NV_ * S_ * DV_];
__device__ float g_eg  [(size_t)B_ * NV_ * S_];
__device__ float g_beta[(size_t)B_ * NV_ * S_];
__device__ float g_o   [(size_t)B_ * NV_ * S_ * DV_];

// bf16 split operands for tensor GEMMs
__device__ __nv_bfloat16 g_hid_hi[(size_t)TOK_ * H_];
__device__ __nv_bfloat16 g_hid_lo[(size_t)TOK_ * H_];
__device__ __nv_bfloat16 g_wqkvz_hi[(size_t)QKVZW * H_];   // transposed [N=12288, K=2048]
__device__ __nv_bfloat16 g_wqkvz_lo[(size_t)QKVZW * H_];
__device__ __nv_bfloat16 g_wout_hi[(size_t)H_ * VDIM_];    // transposed [N=2048, K=4096]
__device__ __nv_bfloat16 g_wout_lo[(size_t)H_ * VDIM_];
__device__ __nv_bfloat16 g_y_hi[(size_t)TOK_ * VDIM_];     // [M=2048, K=4096]
__device__ __nv_bfloat16 g_y_lo[(size_t)TOK_ * VDIM_];

// ---------------- split kernels ---------------------------------------------
__global__ __launch_bounds__(256) void split_kernel(const float* __restrict__ src,
                                                    __nv_bfloat16* __restrict__ hi,
                                                    __nv_bfloat16* __restrict__ lo, int n4)
{
    int i = blockIdx.x * 256 + threadIdx.x;
    if (i >= n4) return;
    float4 x = ((const float4*)src)[i];
    __nv_bfloat16 h0 = __float2bfloat16(x.x), h1 = __float2bfloat16(x.y);
    __nv_bfloat16 h2 = __float2bfloat16(x.z), h3 = __float2bfloat16(x.w);
    __nv_bfloat162 hh0{h0, h1}, hh1{h2, h3};
    __nv_bfloat162 ll0{__float2bfloat16(x.x - __bfloat162float(h0)),
                       __float2bfloat16(x.y - __bfloat162float(h1))};
    __nv_bfloat162 ll1{__float2bfloat16(x.z - __bfloat162float(h2)),
                       __float2bfloat16(x.w - __bfloat162float(h3))};
    ((__nv_bfloat162*)hi)[i * 2]     = hh0;
    ((__nv_bfloat162*)hi)[i * 2 + 1] = hh1;
    ((__nv_bfloat162*)lo)[i * 2]     = ll0;
    ((__nv_bfloat162*)lo)[i * 2 + 1] = ll1;
}

// src [K,N] row-major -> hi/lo [N,K] (transposed), bf16 split
__global__ __launch_bounds__(256) void transpose_split_kernel(const float* __restrict__ src,
                                                              __nv_bfloat16* __restrict__ hi,
                                                              __nv_bfloat16* __restrict__ lo,
                                                              int K, int N)
{
    __shared__ float tile[32][33];
    int nb = blockIdx.x * 32, kb = blockIdx.y * 32;
    int tx = threadIdx.x & 31, ty = threadIdx.x >> 5;   // 32 x 8
#pragma unroll
    for (int j = 0; j < 32; j += 8)
        tile[ty + j][tx] = src[(size_t)(kb + ty + j) * N + nb + tx];
    __syncthreads();
#pragma unroll
    for (int j = 0; j < 32; j += 8) {
        float x = tile[tx][ty + j];                     // src[kb+tx][nb+ty+j]
        __nv_bfloat16 h = __float2bfloat16(x);
        size_t oidx = (size_t)(nb + ty + j) * K + kb + tx;
        hi[oidx] = h;
        lo[oidx] = __float2bfloat16(x - __bfloat162float(h));
    }
}

// ---------------- HMMA split-bf16 GEMM ---------------------------------------
// C[M,N] = A[M,K] * B[N,K]^T; A,B given as hi+lo bf16 (K-major).
// CTA tile 128x128, BK=32, 256 threads (8 warps of 32x64), cp.async double buffer.
// __launch_bounds__(256,2): cap regs at 128 so 2 CTAs/SM co-reside.
#define BKg   32
#define PADK  40          // padded row length (elements)
#define TILEB (128 * PADK * 2)  // 10240 bytes per operand tile

#define LDSM4(r0, r1, r2, r3, addr) \
    asm volatile("ldmatrix.sync.aligned.m8n8.x4.shared.b16 {%0,%1,%2,%3}, [%4];" \
        : "=r"(r0), "=r"(r1), "=r"(r2), "=r"(r3) : "r"(addr))

#define MMA16816(d, a, b) \
    asm volatile("mma.sync.aligned.m16n8k16.row.col.f32.bf16.bf16.f32 " \
        "{%0,%1,%2,%3}, {%4,%5,%6,%7}, {%8,%9}, {%0,%1,%2,%3};" \
        : "+f"((d)[0]), "+f"((d)[1]), "+f"((d)[2]), "+f"((d)[3]) \
        : "r"((a)[0]), "r"((a)[1]), "r"((a)[2]), "r"((a)[3]), "r"((b)[0]), "r"((b)[1]))

#define CP_ASYNC16(saddr, gptr) \
    asm volatile("cp.async.cg.shared.global [%0], [%1], 16;" :: "r"(saddr), "l"(gptr))
#define CP_COMMIT() asm volatile("cp.async.commit_group;" ::: "memory")
#define CP_WAIT1()  asm volatile("cp.async.wait_group 1;" ::: "memory")

__device__ __forceinline__ uint32_t smem_u32_of(const void* p) {
    uint32_t a;
    asm("{ .reg .u64 t; cvta.to.shared.u64 t, %1; cvt.u32.u64 %0, t; }" : "=r"(a) : "l"(p));
    return a;
}

__global__ __launch_bounds__(256, 2) void gemm_bf16s(
    const __nv_bfloat16* __restrict__ Ah, const __nv_bfloat16* __restrict__ Al,
    const __nv_bfloat16* __restrict__ Bh, const __nv_bfloat16* __restrict__ Bl,
    float* __restrict__ C, int M, int N, int K)
{
    extern __shared__ char smem[];
    uint32_t sbase = smem_u32_of(smem);

    int tid = threadIdx.x;
    int wid = tid >> 5, lane = tid & 31;
    int m0 = blockIdx.x * 128;
    int n0 = blockIdx.y * 128;
    int m_w = (wid >> 1) * 32;       // warp M offset (0,32,64,96)
    int n_w = (wid & 1) * 64;        // warp N offset (0,64)

    float acc[2][8][4];
#pragma unroll
    for (int i = 0; i < 2; i++)
#pragma unroll
        for (int j = 0; j < 8; j++)
#pragma unroll
            for (int l = 0; l < 4; l++) acc[i][j][l] = 0.f;

    const int NC = K / BKg;

    // per-lane ldmatrix address components
    int aRow = lane & 15;
    int aColH = (lane >> 4) << 3;            // 0 or 8
    int bRow = (lane & 7) | ((lane & 16) >> 1);  // (lane&7) + (lane&16 ? 8 : 0)
    int bColH = lane & 8;                    // 0 or 8

    // stage loader
    auto load_chunk = [&](int kc, int bsel) {
        int kbase = kc * BKg;
        uint32_t sst = sbase + bsel * (4 * TILEB);
#pragma unroll
        for (int i = 0; i < 8; i++) {
            int idx = i * 256 + tid;         // 0..2047
            int t = idx >> 9;                // 0:Ah 1:Al 2:Bh 3:Bl
            int w = idx & 511;
            int r = w >> 2, c8 = (w & 3) << 3;
            const __nv_bfloat16* src = (t == 0) ? Ah : (t == 1) ? Al : (t == 2) ? Bh : Bl;
            int row = (t < 2) ? (m0 + r) : (n0 + r);
            const __nv_bfloat16* g = src + (size_t)row * K + kbase + c8;
            uint32_t sa = sst + t * TILEB + (uint32_t)(r * PADK + c8) * 2;
            CP_ASYNC16(sa, g);
        }
    };

    load_chunk(0, 0); CP_COMMIT();
    load_chunk(1, 1); CP_COMMIT();

    for (int kc = 0; kc < NC; kc++) {
        CP_WAIT1();
        __syncthreads();

        int bsel = kc & 1;
        uint32_t sst = sbase + bsel * (4 * TILEB);
        uint32_t sAh = sst;
        uint32_t sAl = sst + TILEB;
        uint32_t sBh = sst + 2 * TILEB;
        uint32_t sBl = sst + 3 * TILEB;

#pragma unroll
        for (int ks = 0; ks < 2; ks++) {
            int k0 = ks * 16;
            uint32_t aH[2][4], aL[2][4], bb[8][2];
#pragma unroll
            for (int mt = 0; mt < 2; mt++) {
                uint32_t off = (uint32_t)((m_w + mt * 16 + aRow) * PADK + k0 + aColH) * 2;
                LDSM4(aH[mt][0], aH[mt][1], aH[mt][2], aH[mt][3], sAh + off);
                LDSM4(aL[mt][0], aL[mt][1], aL[mt][2], aL[mt][3], sAl + off);
            }
            // --- bH phase: AhBh + AlBh ---
#pragma unroll
            for (int g2 = 0; g2 < 4; g2++) {
                uint32_t off = (uint32_t)((n_w + g2 * 16 + bRow) * PADK + k0 + bColH) * 2;
                LDSM4(bb[g2 * 2][0], bb[g2 * 2][1], bb[g2 * 2 + 1][0], bb[g2 * 2 + 1][1], sBh + off);
            }
#pragma unroll
            for (int mt = 0; mt < 2; mt++)
#pragma unroll
                for (int nt = 0; nt < 8; nt++) MMA16816(acc[mt][nt], aH[mt], bb[nt]);
#pragma unroll
            for (int mt = 0; mt < 2; mt++)
#pragma unroll
                for (int nt = 0; nt < 8; nt++) MMA16816(acc[mt][nt], aL[mt], bb[nt]);
            // --- bL phase (reuse bb regs): AhBl ---
#pragma unroll
            for (int g2 = 0; g2 < 4; g2++) {
                uint32_t off = (uint32_t)((n_w + g2 * 16 + bRow) * PADK + k0 + bColH) * 2;
                LDSM4(bb[g2 * 2][0], bb[g2 * 2][1], bb[g2 * 2 + 1][0], bb[g2 * 2 + 1][1], sBl + off);
            }
#pragma unroll
            for (int mt = 0; mt < 2; mt++)
#pragma unroll
                for (int nt = 0; nt < 8; nt++) MMA16816(acc[mt][nt], aH[mt], bb[nt]);
        }

        __syncthreads();
        if (kc + 2 < NC) load_chunk(kc + 2, bsel);
        CP_COMMIT();   // empty groups at tail keep wait_group invariant exact
    }

    // epilogue: write f32 C
    int cr = lane >> 2;            // 0..7
    int cc = (lane & 3) * 2;       // 0,2,4,6
#pragma unroll
    for (int mt = 0; mt < 2; mt++) {
#pragma unroll
        for (int nt = 0; nt < 8; nt++) {
            int row = m0 + m_w + mt * 16 + cr;
            int col = n0 + n_w + nt * 8 + cc;
            float2 v0 = {acc[mt][nt][0], acc[mt][nt][1]};
            float2 v1 = {acc[mt][nt][2], acc[mt][nt][3]};
            *(float2*)&C[(size_t)row * N + col]       = v0;
            *(float2*)&C[(size_t)(row + 8) * N + col] = v1;
        }
    }
}
#define GSMEM_BYTES (8 * TILEB)   // 81920

// ---------------- small GEMM: g_ba[2048,64] = A[2048,2048] * W[2048,64] -----
__global__ __launch_bounds__(256) void gemm_ba_kernel(const float* __restrict__ A,
                                                      const float* __restrict__ W)
{
    __shared__ float As[32][64];
    int tid = threadIdx.x;
    int col = tid & 63;
    int rg  = tid >> 6;
    int rowblk = blockIdx.x * 32;

    float acc[8];
#pragma unroll
    for (int r = 0; r < 8; r++) acc[r] = 0.f;

    for (int k0 = 0; k0 < H_; k0 += 64) {
        __syncthreads();
#pragma unroll
        for (int it = 0; it < 8; it++) {
            int idx = it * 256 + tid;
            int rr = idx >> 6, kk = idx & 63;
            As[rr][kk] = A[(size_t)(rowblk + rr) * H_ + k0 + kk];
        }
        __syncthreads();
        for (int kk = 0; kk < 64; kk++) {
            float w = W[(size_t)(k0 + kk) * 64 + col];
#pragma unroll
            for (int rr = 0; rr < 8; rr++) acc[rr] += As[rg * 8 + rr][kk] * w;
        }
    }
#pragma unroll
    for (int rr = 0; rr < 8; rr++)
        g_ba[(size_t)(rowblk + rg * 8 + rr) * 64 + col] = acc[rr];
}

__device__ __forceinline__ float silu_f(float x) { return x / (1.f + expf(-x)); }

// ---------------- q/k depthwise conv4 + silu + l2norm ----------------------
__global__ __launch_bounds__(128) void qk_conv_norm_kernel(const float* __restrict__ conv_w)
{
    int s = blockIdx.x, h = blockIdx.y, b = blockIdx.z;
    int d = threadIdx.x;
    int colq = h * 768 + d;
    int colk = colq + 128;
    int cq = h * 128 + d;
    int ck = 2048 + h * 128 + d;

    float xq = 0.f, xk = 0.f;
#pragma unroll
    for (int j = 0; j < 4; j++) {
        int ss = s - 3 + j;
        if (ss >= 0) {
            const float* row = g_qkvz + (size_t)(b * S_ + ss) * QKVZW;
            xq += conv_w[cq * 4 + j] * row[colq];
            xk += conv_w[ck * 4 + j] * row[colk];
        }
    }
    xq = silu_f(xq);
    xk = silu_f(xk);

    float sq2 = xq * xq, sk2 = xk * xk;
#pragma unroll
    for (int o = 16; o > 0; o >>= 1) {
        sq2 += __shfl_xor_sync(0xffffffffu, sq2, o);
        sk2 += __shfl_xor_sync(0xffffffffu, sk2, o);
    }
    __shared__ float bufq[4], bufk[4];
    if ((d & 31) == 0) { bufq[d >> 5] = sq2; bufk[d >> 5] = sk2; }
    __syncthreads();
    float sumq = bufq[0] + bufq[1] + bufq[2] + bufq[3];
    float sumk = bufk[0] + bufk[1] + bufk[2] + bufk[3];
    float rq = rsqrtf(sumq + 1e-6f) * 0.08838834764831845f;
    float rk = rsqrtf(sumk + 1e-6f);
    size_t base = ((size_t)(b * NK_ + h) * S_ + s) * DK_ + d;
    g_q[base] = xq * rq;
    g_k[base] = xk * rk;
}

// ---------------- v conv4 + silu, beta / exp(g) gates ----------------------
__global__ __launch_bounds__(128) void v_conv_gate_kernel(const float* __restrict__ conv_w,
                                                          const float* __restrict__ dt_bias,
                                                          const float* __restrict__ A_log)
{
    int s = blockIdx.x, vh = blockIdx.y, b = blockIdx.z;
    int d = threadIdx.x;
    int kh = vh >> 1, sub = vh & 1;
    int col = kh * 768 + 256 + sub * 128 + d;
    int cc  = 4096 + vh * 128 + d;

    float x = 0.f;
#pragma unroll
    for (int j = 0; j < 4; j++) {
        int ss = s - 3 + j;
        if (ss >= 0)
            x += conv_w[cc * 4 + j] * g_qkvz[(size_t)(b * S_ + ss) * QKVZW + col];
    }
    g_v[((size_t)(b * NV_ + vh) * S_ + s) * DV_ + d] = silu_f(x);

    if (d == 0) {
        const float* barow = g_ba + (size_t)(b * S_ + s) * 64;
        float bb = barow[kh * 4 + sub];
        float aa = barow[kh * 4 + 2 + sub];
        float beta = 1.f / (1.f + expf(-bb));
        float xx = aa + dt_bias[vh];
        float sp = (xx > 20.f) ? xx : log1pf(expf(xx));
        float g  = -expf(A_log[vh]) * sp;
        g_beta[(size_t)(b * NV_ + vh) * S_ + s] = beta;
        g_eg  [(size_t)(b * NV_ + vh) * S_ + s] = expf(g);
    }
}

// ---------------- gated delta-rule scan ------------------------------------
#define SCAN_T 32
__global__ __launch_bounds__(128) void scan_kernel()
{
    int flat = blockIdx.x;
    int sl = flat & 3;
    int vh = (flat >> 2) & 31;
    int b  = flat >> 7;
    int kh = vh >> 1;

    int tid = threadIdx.x;
    int warp = tid >> 5, lane = tid & 31;
    int c = warp * 8 + (lane >> 2);
    int r = lane & 3;
    int dkb = r * 32;

    __shared__ float sk[SCAN_T][128];
    __shared__ float sq[SCAN_T][128];
    __shared__ float sv[SCAN_T][32];
    __shared__ float seg[SCAN_T], sb[SCAN_T];

    const float* kbase  = g_k + (size_t)(b * NK_ + kh) * S_ * DK_;
    const float* qbase  = g_q + (size_t)(b * NK_ + kh) * S_ * DK_;
    const float* vbase  = g_v + (size_t)(b * NV_ + vh) * S_ * DV_ + sl * 32;
    const float* egbase = g_eg   + (size_t)(b * NV_ + vh) * S_;
    const float* btbase = g_beta + (size_t)(b * NV_ + vh) * S_;
    float* obase = g_o + (size_t)(b * NV_ + vh) * S_ * DV_ + sl * 32;

    float st[32];
#pragma unroll
    for (int i = 0; i < 32; i++) st[i] = 0.f;

    for (int s0 = 0; s0 < S_; s0 += SCAN_T) {
#pragma unroll
        for (int it = 0; it < 8; it++) {
            int idx = it * 128 + tid;
            int t = idx >> 5, d4 = (idx & 31) << 2;
            *(float4*)&sk[t][d4] = *(const float4*)&kbase[(size_t)(s0 + t) * DK_ + d4];
            *(float4*)&sq[t][d4] = *(const float4*)&qbase[(size_t)(s0 + t) * DK_ + d4];
        }
#pragma unroll
        for (int it = 0; it < 2; it++) {
            int idx = it * 128 + tid;
            int t = idx >> 3, d4 = (idx & 7) << 2;
            *(float4*)&sv[t][d4] = *(const float4*)&vbase[(size_t)(s0 + t) * DV_ + d4];
        }
        if (tid < SCAN_T) { seg[tid] = egbase[s0 + tid]; sb[tid] = btbase[s0 + tid]; }
        __syncthreads();

        for (int t = 0; t < SCAN_T; t++) {
            float eg = seg[t], bt = sb[t], vt = sv[t][c];
            float kreg[32];
#pragma unroll
            for (int i4 = 0; i4 < 8; i4++) {
                float4 kk = *(float4*)&sk[t][dkb + i4 * 4];
                kreg[i4 * 4 + 0] = kk.x; kreg[i4 * 4 + 1] = kk.y;
                kreg[i4 * 4 + 2] = kk.z; kreg[i4 * 4 + 3] = kk.w;
            }
            float kv = 0.f;
#pragma unroll
            for (int i = 0; i < 32; i++) { st[i] *= eg; kv += st[i] * kreg[i]; }
            kv += __shfl_xor_sync(0xffffffffu, kv, 1);
            kv += __shfl_xor_sync(0xffffffffu, kv, 2);
            float delta = (vt - kv) * bt;
            float o = 0.f;
#pragma unroll
            for (int i4 = 0; i4 < 8; i4++) {
                float4 qq = *(float4*)&sq[t][dkb + i4 * 4];
                st[i4 * 4 + 0] += kreg[i4 * 4 + 0] * delta; o += qq.x * st[i4 * 4 + 0];
                st[i4 * 4 + 1] += kreg[i4 * 4 + 1] * delta; o += qq.y * st[i4 * 4 + 1];
                st[i4 * 4 + 2] += kreg[i4 * 4 + 2] * delta; o += qq.z * st[i4 * 4 + 2];
                st[i4 * 4 + 3] += kreg[i4 * 4 + 3] * delta; o += qq.w * st[i4 * 4 + 3];
            }
            o += __shfl_xor_sync(0xffffffffu, o, 1);
            o += __shfl_xor_sync(0xffffffffu, o, 2);
            if (r == 0) obase[(size_t)(s0 + t) * DV_ + c] = o;
        }
        __syncthreads();
    }
}

// ---------------- gated RMSNorm (emits split-bf16 y) ------------------------
__global__ __launch_bounds__(128) void rmsnorm_kernel(const float* __restrict__ norm_w)
{
    int s = blockIdx.x, vh = blockIdx.y, b = blockIdx.z;
    int d = threadIdx.x;
    float x = g_o[((size_t)(b * NV_ + vh) * S_ + s) * DV_ + d];
    float z = g_qkvz[(size_t)(b * S_ + s) * QKVZW + (vh >> 1) * 768 + 512 + (vh & 1) * 128 + d];
    float xg = x * silu_f(z);

    float ss = xg * xg;
#pragma unroll
    for (int o = 16; o > 0; o >>= 1) ss += __shfl_xor_sync(0xffffffffu, ss, o);
    __shared__ float buf[4];
    if ((d & 31) == 0) buf[d >> 5] = ss;
    __syncthreads();
    float sum = buf[0] + buf[1] + buf[2] + buf[3];
    float y = xg * rsqrtf(sum * (1.f / 128.f) + 1e-6f) * norm_w[d];
    size_t oidx = (size_t)(b * S_ + s) * VDIM_ + vh * 128 + d;
    __nv_bfloat16 h = __float2bfloat16(y);
    g_y_hi[oidx] = h;
    g_y_lo[oidx] = __float2bfloat16(y - __bfloat162float(h));
}

// ---------------- launch ----------------------------------------------------
extern "C" void kernel_launch(void* const* d_in, const int* in_sizes, int n_in,
                              void* d_out, int out_size)
{
    const float* hidden  = (const float*)d_in[0];
    const float* w_qkvz  = (const float*)d_in[1];
    const float* w_ba    = (const float*)d_in[2];
    const float* conv_w  = (const float*)d_in[3];
    const float* dt_bias = (const float*)d_in[4];
    const float* A_log   = (const float*)d_in[5];
    const float* norm_w  = (const float*)d_in[6];
    const float* w_out   = (const float*)d_in[7];
    float* out = (float*)d_out;

    float *qkvz_p = nullptr;
    cudaGetSymbolAddress((void**)&qkvz_p, g_qkvz);
    __nv_bfloat16 *hid_hi, *hid_lo, *wq_hi, *wq_lo, *wo_hi, *wo_lo, *y_hi, *y_lo;
    cudaGetSymbolAddress((void**)&hid_hi, g_hid_hi);
    cudaGetSymbolAddress((void**)&hid_lo, g_hid_lo);
    cudaGetSymbolAddress((void**)&wq_hi, g_wqkvz_hi);
    cudaGetSymbolAddress((void**)&wq_lo, g_wqkvz_lo);
    cudaGetSymbolAddress((void**)&wo_hi, g_wout_hi);
    cudaGetSymbolAddress((void**)&wo_lo, g_wout_lo);
    cudaGetSymbolAddress((void**)&y_hi, g_y_hi);
    cudaGetSymbolAddress((void**)&y_lo, g_y_lo);

    cudaFuncSetAttribute(gemm_bf16s, cudaFuncAttributeMaxDynamicSharedMemorySize, GSMEM_BYTES);

    // 0) precision splits (+ weight transposes to [N,K])
    split_kernel<<<(TOK_ * H_ / 4 + 255) / 256, 256>>>(hidden, hid_hi, hid_lo, TOK_ * H_ / 4);
    transpose_split_kernel<<<dim3(QKVZW / 32, H_ / 32), 256>>>(w_qkvz, wq_hi, wq_lo, H_, QKVZW);
    transpose_split_kernel<<<dim3(H_ / 32, VDIM_ / 32), 256>>>(w_out, wo_hi, wo_lo, VDIM_, H_);

    // 1) projections
    gemm_bf16s<<<dim3(TOK_ / 128, QKVZW / 128), 256, GSMEM_BYTES>>>(
        hid_hi, hid_lo, wq_hi, wq_lo, qkvz_p, TOK_, QKVZW, H_);
    gemm_ba_kernel<<<TOK_ / 32, 256>>>(hidden, w_ba);

    // 2) conv + activations + norms + gates
    qk_conv_norm_kernel<<<dim3(S_, NK_, B_), 128>>>(conv_w);
    v_conv_gate_kernel<<<dim3(S_, NV_, B_), 128>>>(conv_w, dt_bias, A_log);

    // 3) gated delta-rule recurrence
    scan_kernel<<<B_ * NV_ * 4, 128>>>();

    // 4) gated RMSNorm -> split-bf16 y
    rmsnorm_kernel<<<dim3(S_, NV_, B_), 128>>>(norm_w);

    // 5) output projection
    gemm_bf16s<<<dim3(TOK_ / 128, H_ / 128), 256, GSMEM_BYTES>>>(
        y_hi, y_lo, wo_hi, wo_lo, out, TOK_, H_, VDIM_);
}

// round 7
// speedup vs baseline: 2.2669x; 1.2818x over previous
#include <cuda_runtime.h>
#include <cuda_bf16.h>
#include <math.h>
#include <cstdint>

// ---------------- problem constants ----------------
#define B_    2
#define S_    1024
#define H_    2048
#define NK_   16
#define NV_   32
#define DK_   128
#define DV_   128
#define QKVZW 12288     // 2*KDIM + 2*VDIM
#define KDIM_ 2048
#define VDIM_ 4096
#define TOK_  (B_*S_)   // 2048

// ---------------- scratch (device globals; no cudaMalloc allowed) ----------
__device__ float g_qkvz[(size_t)TOK_ * QKVZW];         // [B*S, 12288]
__device__ float g_ba  [(size_t)TOK_ * 64];            // [B*S, 64]
__device__ float g_q   [(size_t)B_ * NK_ * S_ * DK_];
__device__ float g_k   [(size_t)B_ * NK_ * S_ * DK_];
__device__ float g_kq  [(size_t)B_ * NK_ * S_];        // dot(q_norm, k_norm) per (b,h,s)
__device__ float g_v   [(size_t)B_ * NV_ * S_ * DV_];
__device__ float g_eg  [(size_t)B_ * NV_ * S_];
__device__ float g_beta[(size_t)B_ * NV_ * S_];
__device__ float g_o   [(size_t)B_ * NV_ * S_ * DV_];

// bf16 split operands for tensor GEMMs
__device__ __nv_bfloat16 g_hid_hi[(size_t)TOK_ * H_];
__device__ __nv_bfloat16 g_hid_lo[(size_t)TOK_ * H_];
__device__ __nv_bfloat16 g_wqkvz_hi[(size_t)QKVZW * H_];   // transposed [N=12288, K=2048]
__device__ __nv_bfloat16 g_wqkvz_lo[(size_t)QKVZW * H_];
__device__ __nv_bfloat16 g_wout_hi[(size_t)H_ * VDIM_];    // transposed [N=2048, K=4096]
__device__ __nv_bfloat16 g_wout_lo[(size_t)H_ * VDIM_];
__device__ __nv_bfloat16 g_y_hi[(size_t)TOK_ * VDIM_];     // [M=2048, K=4096]
__device__ __nv_bfloat16 g_y_lo[(size_t)TOK_ * VDIM_];

// ---------------- split kernels ---------------------------------------------
__global__ __launch_bounds__(256) void split_kernel(const float* __restrict__ src,
                                                    __nv_bfloat16* __restrict__ hi,
                                                    __nv_bfloat16* __restrict__ lo, int n4)
{
    int i = blockIdx.x * 256 + threadIdx.x;
    if (i >= n4) return;
    float4 x = ((const float4*)src)[i];
    __nv_bfloat16 h0 = __float2bfloat16(x.x), h1 = __float2bfloat16(x.y);
    __nv_bfloat16 h2 = __float2bfloat16(x.z), h3 = __float2bfloat16(x.w);
    __nv_bfloat162 hh0{h0, h1}, hh1{h2, h3};
    __nv_bfloat162 ll0{__float2bfloat16(x.x - __bfloat162float(h0)),
                       __float2bfloat16(x.y - __bfloat162float(h1))};
    __nv_bfloat162 ll1{__float2bfloat16(x.z - __bfloat162float(h2)),
                       __float2bfloat16(x.w - __bfloat162float(h3))};
    ((__nv_bfloat162*)hi)[i * 2]     = hh0;
    ((__nv_bfloat162*)hi)[i * 2 + 1] = hh1;
    ((__nv_bfloat162*)lo)[i * 2]     = ll0;
    ((__nv_bfloat162*)lo)[i * 2 + 1] = ll1;
}

// src [K,N] row-major -> hi/lo [N,K] (transposed), bf16 split
__global__ __launch_bounds__(256) void transpose_split_kernel(const float* __restrict__ src,
                                                              __nv_bfloat16* __restrict__ hi,
                                                              __nv_bfloat16* __restrict__ lo,
                                                              int K, int N)
{
    __shared__ float tile[32][33];
    int nb = blockIdx.x * 32, kb = blockIdx.y * 32;
    int tx = threadIdx.x & 31, ty = threadIdx.x >> 5;   // 32 x 8
#pragma unroll
    for (int j = 0; j < 32; j += 8)
        tile[ty + j][tx] = src[(size_t)(kb + ty + j) * N + nb + tx];
    __syncthreads();
#pragma unroll
    for (int j = 0; j < 32; j += 8) {
        float x = tile[tx][ty + j];                     // src[kb+tx][nb+ty+j]
        __nv_bfloat16 h = __float2bfloat16(x);
        size_t oidx = (size_t)(nb + ty + j) * K + kb + tx;
        hi[oidx] = h;
        lo[oidx] = __float2bfloat16(x - __bfloat162float(h));
    }
}

// ---------------- HMMA split-bf16 GEMM ---------------------------------------
// C[M,N] = A[M,K] * B[N,K]^T; A,B given as hi+lo bf16 (K-major).
// CTA tile 128x128, BK=16, 256 threads (8 warps of 32x64),
// 4-stage cp.async pipeline, ONE __syncthreads per stage, loads issued early.
// PADK=24 elems -> 48-byte rows: 16B-aligned (cp.async/ldmatrix legal) and
// conflict-free (8 rows at 12-word stride tile all 32 banks).
#define BK16   16
#define PADK   24
#define TILE16 (128 * PADK * 2)    // 6144 bytes per operand tile
#define STAGEB (4 * TILE16)        // 24576 bytes per stage
#define GSMEM_BYTES (4 * STAGEB)   // 98304 (2 CTAs = 192KB < 228KB)

#define LDSM4(r0, r1, r2, r3, addr) \
    asm volatile("ldmatrix.sync.aligned.m8n8.x4.shared.b16 {%0,%1,%2,%3}, [%4];" \
        : "=r"(r0), "=r"(r1), "=r"(r2), "=r"(r3) : "r"(addr))

#define MMA16816(d, a, b) \
    asm volatile("mma.sync.aligned.m16n8k16.row.col.f32.bf16.bf16.f32 " \
        "{%0,%1,%2,%3}, {%4,%5,%6,%7}, {%8,%9}, {%0,%1,%2,%3};" \
        : "+f"((d)[0]), "+f"((d)[1]), "+f"((d)[2]), "+f"((d)[3]) \
        : "r"((a)[0]), "r"((a)[1]), "r"((a)[2]), "r"((a)[3]), "r"((b)[0]), "r"((b)[1]))

#define CP_ASYNC16(saddr, gptr) \
    asm volatile("cp.async.cg.shared.global [%0], [%1], 16;" :: "r"(saddr), "l"(gptr))
#define CP_COMMIT() asm volatile("cp.async.commit_group;" ::: "memory")
#define CP_WAIT2()  asm volatile("cp.async.wait_group 2;" ::: "memory")

__device__ __forceinline__ uint32_t smem_u32_of(const void* p) {
    uint32_t a;
    asm("{ .reg .u64 t; cvta.to.shared.u64 t, %1; cvt.u32.u64 %0, t; }" : "=r"(a) : "l"(p));
    return a;
}

__global__ __launch_bounds__(256, 2) void gemm_bf16s(
    const __nv_bfloat16* __restrict__ Ah, const __nv_bfloat16* __restrict__ Al,
    const __nv_bfloat16* __restrict__ Bh, const __nv_bfloat16* __restrict__ Bl,
    float* __restrict__ C, int M, int N, int K)
{
    extern __shared__ __align__(16) char smem[];
    uint32_t sbase = smem_u32_of(smem);

    int tid = threadIdx.x;
    int wid = tid >> 5, lane = tid & 31;
    int m0 = blockIdx.x * 128;
    int n0 = blockIdx.y * 128;
    int m_w = (wid >> 1) * 32;       // warp M offset (0,32,64,96)
    int n_w = (wid & 1) * 64;        // warp N offset (0,64)

    float acc[2][8][4];
#pragma unroll
    for (int i = 0; i < 2; i++)
#pragma unroll
        for (int j = 0; j < 8; j++)
#pragma unroll
            for (int l = 0; l < 4; l++) acc[i][j][l] = 0.f;

    const int NC = K / BK16;

    // per-lane ldmatrix address components
    int aRow = lane & 15;
    int aColH = (lane >> 4) << 3;                // 0 or 8
    int bRow = (lane & 7) | ((lane & 16) >> 1);  // 0..15
    int bColH = lane & 8;                        // 0 or 8

    // stage loader: 4 tiles x 128 rows x 16 elems (32B/row) = 1024 cp.async of 16B
    auto load_chunk = [&](int kc, int slot) {
        int kbase = kc * BK16;
        uint32_t sst = sbase + slot * STAGEB;
#pragma unroll
        for (int i = 0; i < 4; i++) {
            int idx = i * 256 + tid;         // 0..1023
            int t = idx >> 8;                // 0:Ah 1:Al 2:Bh 3:Bl
            int w = idx & 255;
            int r = w >> 1, c8 = (w & 1) << 3;
            const __nv_bfloat16* src = (t == 0) ? Ah : (t == 1) ? Al : (t == 2) ? Bh : Bl;
            int row = (t < 2) ? (m0 + r) : (n0 + r);
            const __nv_bfloat16* g = src + (size_t)row * K + kbase + c8;
            uint32_t sa = sst + t * TILE16 + (uint32_t)(r * PADK + c8) * 2;
            CP_ASYNC16(sa, g);
        }
    };

    load_chunk(0, 0); CP_COMMIT();
    load_chunk(1, 1); CP_COMMIT();
    load_chunk(2, 2); CP_COMMIT();

    for (int kc = 0; kc < NC; kc++) {
        CP_WAIT2();            // stage kc complete
        __syncthreads();       // all warps done with the slot being refilled
        if (kc + 3 < NC) load_chunk(kc + 3, (kc + 3) & 3);
        CP_COMMIT();           // keep group count invariant (empty ok)

        uint32_t sst = sbase + (kc & 3) * STAGEB;
        uint32_t sAh = sst;
        uint32_t sAl = sst + TILE16;
        uint32_t sBh = sst + 2 * TILE16;
        uint32_t sBl = sst + 3 * TILE16;

        uint32_t aH[2][4], aL[2][4], bb[8][2];
#pragma unroll
        for (int mt = 0; mt < 2; mt++) {
            uint32_t off = (uint32_t)((m_w + mt * 16 + aRow) * PADK + aColH) * 2;
            LDSM4(aH[mt][0], aH[mt][1], aH[mt][2], aH[mt][3], sAh + off);
            LDSM4(aL[mt][0], aL[mt][1], aL[mt][2], aL[mt][3], sAl + off);
        }
        // --- bH phase: AhBh + AlBh ---
#pragma unroll
        for (int g2 = 0; g2 < 4; g2++) {
            uint32_t off = (uint32_t)((n_w + g2 * 16 + bRow) * PADK + bColH) * 2;
            LDSM4(bb[g2 * 2][0], bb[g2 * 2][1], bb[g2 * 2 + 1][0], bb[g2 * 2 + 1][1], sBh + off);
        }
#pragma unroll
        for (int mt = 0; mt < 2; mt++)
#pragma unroll
            for (int nt = 0; nt < 8; nt++) MMA16816(acc[mt][nt], aH[mt], bb[nt]);
#pragma unroll
        for (int mt = 0; mt < 2; mt++)
#pragma unroll
            for (int nt = 0; nt < 8; nt++) MMA16816(acc[mt][nt], aL[mt], bb[nt]);
        // --- bL phase (reuse bb regs): AhBl ---
#pragma unroll
        for (int g2 = 0; g2 < 4; g2++) {
            uint32_t off = (uint32_t)((n_w + g2 * 16 + bRow) * PADK + bColH) * 2;
            LDSM4(bb[g2 * 2][0], bb[g2 * 2][1], bb[g2 * 2 + 1][0], bb[g2 * 2 + 1][1], sBl + off);
        }
#pragma unroll
        for (int mt = 0; mt < 2; mt++)
#pragma unroll
            for (int nt = 0; nt < 8; nt++) MMA16816(acc[mt][nt], aH[mt], bb[nt]);
    }

    // epilogue: write f32 C
    int cr = lane >> 2;            // 0..7
    int cc = (lane & 3) * 2;       // 0,2,4,6
#pragma unroll
    for (int mt = 0; mt < 2; mt++) {
#pragma unroll
        for (int nt = 0; nt < 8; nt++) {
            int row = m0 + m_w + mt * 16 + cr;
            int col = n0 + n_w + nt * 8 + cc;
            float2 v0 = {acc[mt][nt][0], acc[mt][nt][1]};
            float2 v1 = {acc[mt][nt][2], acc[mt][nt][3]};
            *(float2*)&C[(size_t)row * N + col]       = v0;
            *(float2*)&C[(size_t)(row + 8) * N + col] = v1;
        }
    }
}

// ---------------- small GEMM: g_ba[2048,64] = A[2048,2048] * W[2048,64] -----
__global__ __launch_bounds__(256) void gemm_ba_kernel(const float* __restrict__ A,
                                                      const float* __restrict__ W)
{
    __shared__ float As[32][64];
    int tid = threadIdx.x;
    int col = tid & 63;
    int rg  = tid >> 6;
    int rowblk = blockIdx.x * 32;

    float acc[8];
#pragma unroll
    for (int r = 0; r < 8; r++) acc[r] = 0.f;

    for (int k0 = 0; k0 < H_; k0 += 64) {
        __syncthreads();
#pragma unroll
        for (int it = 0; it < 8; it++) {
            int idx = it * 256 + tid;
            int rr = idx >> 6, kk = idx & 63;
            As[rr][kk] = A[(size_t)(rowblk + rr) * H_ + k0 + kk];
        }
        __syncthreads();
        for (int kk = 0; kk < 64; kk++) {
            float w = W[(size_t)(k0 + kk) * 64 + col];
#pragma unroll
            for (int rr = 0; rr < 8; rr++) acc[rr] += As[rg * 8 + rr][kk] * w;
        }
    }
#pragma unroll
    for (int rr = 0; rr < 8; rr++)
        g_ba[(size_t)(rowblk + rg * 8 + rr) * 64 + col] = acc[rr];
}

__device__ __forceinline__ float silu_f(float x) { return x / (1.f + expf(-x)); }

// ---------------- q/k depthwise conv4 + silu + l2norm + kq dot --------------
__global__ __launch_bounds__(128) void qk_conv_norm_kernel(const float* __restrict__ conv_w)
{
    int s = blockIdx.x, h = blockIdx.y, b = blockIdx.z;
    int d = threadIdx.x;
    int colq = h * 768 + d;
    int colk = colq + 128;
    int cq = h * 128 + d;
    int ck = 2048 + h * 128 + d;

    float xq = 0.f, xk = 0.f;
#pragma unroll
    for (int j = 0; j < 4; j++) {
        int ss = s - 3 + j;
        if (ss >= 0) {
            const float* row = g_qkvz + (size_t)(b * S_ + ss) * QKVZW;
            xq += conv_w[cq * 4 + j] * row[colq];
            xk += conv_w[ck * 4 + j] * row[colk];
        }
    }
    xq = silu_f(xq);
    xk = silu_f(xk);

    float sq2 = xq * xq, sk2 = xk * xk;
#pragma unroll
    for (int o = 16; o > 0; o >>= 1) {
        sq2 += __shfl_xor_sync(0xffffffffu, sq2, o);
        sk2 += __shfl_xor_sync(0xffffffffu, sk2, o);
    }
    __shared__ float bufq[4], bufk[4], bufp[4];
    if ((d & 31) == 0) { bufq[d >> 5] = sq2; bufk[d >> 5] = sk2; }
    __syncthreads();
    float sumq = bufq[0] + bufq[1] + bufq[2] + bufq[3];
    float sumk = bufk[0] + bufk[1] + bufk[2] + bufk[3];
    float rq = rsqrtf(sumq + 1e-6f) * 0.08838834764831845f;
    float rk = rsqrtf(sumk + 1e-6f);
    float qv = xq * rq, kv = xk * rk;
    size_t base = ((size_t)(b * NK_ + h) * S_ + s) * DK_ + d;
    g_q[base] = qv;
    g_k[base] = kv;

    // dot(q,k) for the scan
    float pp = qv * kv;
#pragma unroll
    for (int o = 16; o > 0; o >>= 1) pp += __shfl_xor_sync(0xffffffffu, pp, o);
    if ((d & 31) == 0) bufp[d >> 5] = pp;
    __syncthreads();
    if (d == 0)
        g_kq[(size_t)(b * NK_ + h) * S_ + s] = bufp[0] + bufp[1] + bufp[2] + bufp[3];
}

// ---------------- v conv4 + silu, beta / exp(g) gates ----------------------
__global__ __launch_bounds__(128) void v_conv_gate_kernel(const float* __restrict__ conv_w,
                                                          const float* __restrict__ dt_bias,
                                                          const float* __restrict__ A_log)
{
    int s = blockIdx.x, vh = blockIdx.y, b = blockIdx.z;
    int d = threadIdx.x;
    int kh = vh >> 1, sub = vh & 1;
    int col = kh * 768 + 256 + sub * 128 + d;
    int cc  = 4096 + vh * 128 + d;

    float x = 0.f;
#pragma unroll
    for (int j = 0; j < 4; j++) {
        int ss = s - 3 + j;
        if (ss >= 0)
            x += conv_w[cc * 4 + j] * g_qkvz[(size_t)(b * S_ + ss) * QKVZW + col];
    }
    g_v[((size_t)(b * NV_ + vh) * S_ + s) * DV_ + d] = silu_f(x);

    if (d == 0) {
        const float* barow = g_ba + (size_t)(b * S_ + s) * 64;
        float bb = barow[kh * 4 + sub];
        float aa = barow[kh * 4 + 2 + sub];
        float beta = 1.f / (1.f + expf(-bb));
        float xx = aa + dt_bias[vh];
        float sp = (xx > 20.f) ? xx : log1pf(expf(xx));
        float g  = -expf(A_log[vh]) * sp;
        g_beta[(size_t)(b * NV_ + vh) * S_ + s] = beta;
        g_eg  [(size_t)(b * NV_ + vh) * S_ + s] = expf(g);
    }
}

// ---------------- gated delta-rule scan ------------------------------------
// kv = eg*dot(st,k); o = eg*dot(st,q) + delta*dot(k,q) (dot(k,q) precomputed).
// Skewed smem index kills the 4-way LDS bank conflict.
#define SCAN_T 32
#define SKROW  144      // 128 + skew room
#define SKIDX(d) ((d) + (((d) >> 5) << 2))   // insert 4-word gap per 32 words

__global__ __launch_bounds__(128) void scan_kernel()
{
    int flat = blockIdx.x;
    int sl = flat & 3;
    int vh = (flat >> 2) & 31;
    int b  = flat >> 7;
    int kh = vh >> 1;

    int tid = threadIdx.x;
    int warp = tid >> 5, lane = tid & 31;
    int c = warp * 8 + (lane >> 2);   // 0..31 (column within slice)
    int r = lane & 3;                 // dk quarter

    __shared__ __align__(16) float sk[SCAN_T][SKROW];
    __shared__ __align__(16) float sq[SCAN_T][SKROW];
    __shared__ __align__(16) float sv[SCAN_T][32];
    __shared__ float seg[SCAN_T], sb[SCAN_T], skq[SCAN_T];

    const float* kbase  = g_k + (size_t)(b * NK_ + kh) * S_ * DK_;
    const float* qbase  = g_q + (size_t)(b * NK_ + kh) * S_ * DK_;
    const float* kqbase = g_kq + (size_t)(b * NK_ + kh) * S_;
    const float* vbase  = g_v + (size_t)(b * NV_ + vh) * S_ * DV_ + sl * 32;
    const float* egbase = g_eg   + (size_t)(b * NV_ + vh) * S_;
    const float* btbase = g_beta + (size_t)(b * NV_ + vh) * S_;
    float* obase = g_o + (size_t)(b * NV_ + vh) * S_ * DV_ + sl * 32;

    float st[32];
#pragma unroll
    for (int i = 0; i < 32; i++) st[i] = 0.f;

    for (int s0 = 0; s0 < S_; s0 += SCAN_T) {
#pragma unroll
        for (int it = 0; it < 8; it++) {
            int idx = it * 128 + tid;          // float4 index, 1024 total
            int t = idx >> 5, d4 = (idx & 31) << 2;
            int p = SKIDX(d4);
            *(float4*)&sk[t][p] = *(const float4*)&kbase[(size_t)(s0 + t) * DK_ + d4];
            *(float4*)&sq[t][p] = *(const float4*)&qbase[(size_t)(s0 + t) * DK_ + d4];
        }
#pragma unroll
        for (int it = 0; it < 2; it++) {
            int idx = it * 128 + tid;
            int t = idx >> 3, d4 = (idx & 7) << 2;
            *(float4*)&sv[t][d4] = *(const float4*)&vbase[(size_t)(s0 + t) * DV_ + d4];
        }
        if (tid < SCAN_T) {
            seg[tid] = egbase[s0 + tid];
            sb[tid]  = btbase[s0 + tid];
            skq[tid] = kqbase[s0 + tid];
        }
        __syncthreads();

        for (int t = 0; t < SCAN_T; t++) {
            float eg = seg[t], bt = sb[t], vt = sv[t][c], kq = skq[t];
            float kreg[32], qreg[32];
            int pb = r * 36;    // SKIDX(r*32 + x) = r*36 + x for x<32
#pragma unroll
            for (int i4 = 0; i4 < 8; i4++) {
                float4 kk = *(float4*)&sk[t][pb + i4 * 4];
                kreg[i4 * 4 + 0] = kk.x; kreg[i4 * 4 + 1] = kk.y;
                kreg[i4 * 4 + 2] = kk.z; kreg[i4 * 4 + 3] = kk.w;
                float4 qq = *(float4*)&sq[t][pb + i4 * 4];
                qreg[i4 * 4 + 0] = qq.x; qreg[i4 * 4 + 1] = qq.y;
                qreg[i4 * 4 + 2] = qq.z; qreg[i4 * 4 + 3] = qq.w;
            }
            // tree dots: dot1 = st.k, dot2 = st.q (4 partials each)
            float d1a = 0.f, d1b = 0.f, d1c = 0.f, d1d = 0.f;
            float d2a = 0.f, d2b = 0.f, d2c = 0.f, d2d = 0.f;
#pragma unroll
            for (int i = 0; i < 8; i++) {
                d1a += st[i]      * kreg[i];
                d1b += st[i + 8]  * kreg[i + 8];
                d1c += st[i + 16] * kreg[i + 16];
                d1d += st[i + 24] * kreg[i + 24];
                d2a += st[i]      * qreg[i];
                d2b += st[i + 8]  * qreg[i + 8];
                d2c += st[i + 16] * qreg[i + 16];
                d2d += st[i + 24] * qreg[i + 24];
            }
            float dot1 = (d1a + d1b) + (d1c + d1d);
            float dot2 = (d2a + d2b) + (d2c + d2d);
            dot1 += __shfl_xor_sync(0xffffffffu, dot1, 1);
            dot1 += __shfl_xor_sync(0xffffffffu, dot1, 2);
            float delta = (vt - eg * dot1) * bt;
            dot2 += __shfl_xor_sync(0xffffffffu, dot2, 1);
            dot2 += __shfl_xor_sync(0xffffffffu, dot2, 2);
            // state update (independent per element, 1-FFMA chain)
#pragma unroll
            for (int i = 0; i < 32; i++)
                st[i] = fmaf(st[i], eg, kreg[i] * delta);
            float o = fmaf(delta, kq, eg * dot2);
            if (r == 0) obase[(size_t)(s0 + t) * DV_ + c] = o;
        }
        __syncthreads();
    }
}

// ---------------- gated RMSNorm (emits split-bf16 y) ------------------------
__global__ __launch_bounds__(128) void rmsnorm_kernel(const float* __restrict__ norm_w)
{
    int s = blockIdx.x, vh = blockIdx.y, b = blockIdx.z;
    int d = threadIdx.x;
    float x = g_o[((size_t)(b * NV_ + vh) * S_ + s) * DV_ + d];
    float z = g_qkvz[(size_t)(b * S_ + s) * QKVZW + (vh >> 1) * 768 + 512 + (vh & 1) * 128 + d];
    float xg = x * silu_f(z);

    float ss = xg * xg;
#pragma unroll
    for (int o = 16; o > 0; o >>= 1) ss += __shfl_xor_sync(0xffffffffu, ss, o);
    __shared__ float buf[4];
    if ((d & 31) == 0) buf[d >> 5] = ss;
    __syncthreads();
    float sum = buf[0] + buf[1] + buf[2] + buf[3];
    float y = xg * rsqrtf(sum * (1.f / 128.f) + 1e-6f) * norm_w[d];
    size_t oidx = (size_t)(b * S_ + s) * VDIM_ + vh * 128 + d;
    __nv_bfloat16 h = __float2bfloat16(y);
    g_y_hi[oidx] = h;
    g_y_lo[oidx] = __float2bfloat16(y - __bfloat162float(h));
}

// ---------------- launch ----------------------------------------------------
extern "C" void kernel_launch(void* const* d_in, const int* in_sizes, int n_in,
                              void* d_out, int out_size)
{
    const float* hidden  = (const float*)d_in[0];
    const float* w_qkvz  = (const float*)d_in[1];
    const float* w_ba    = (const float*)d_in[2];
    const float* conv_w  = (const float*)d_in[3];
    const float* dt_bias = (const float*)d_in[4];
    const float* A_log   = (const float*)d_in[5];
    const float* norm_w  = (const float*)d_in[6];
    const float* w_out   = (const float*)d_in[7];
    float* out = (float*)d_out;

    float *qkvz_p = nullptr;
    cudaGetSymbolAddress((void**)&qkvz_p, g_qkvz);
    __nv_bfloat16 *hid_hi, *hid_lo, *wq_hi, *wq_lo, *wo_hi, *wo_lo, *y_hi, *y_lo;
    cudaGetSymbolAddress((void**)&hid_hi, g_hid_hi);
    cudaGetSymbolAddress((void**)&hid_lo, g_hid_lo);
    cudaGetSymbolAddress((void**)&wq_hi, g_wqkvz_hi);
    cudaGetSymbolAddress((void**)&wq_lo, g_wqkvz_lo);
    cudaGetSymbolAddress((void**)&wo_hi, g_wout_hi);
    cudaGetSymbolAddress((void**)&wo_lo, g_wout_lo);
    cudaGetSymbolAddress((void**)&y_hi, g_y_hi);
    cudaGetSymbolAddress((void**)&y_lo, g_y_lo);

    cudaFuncSetAttribute(gemm_bf16s, cudaFuncAttributeMaxDynamicSharedMemorySize, GSMEM_BYTES);

    // 0) precision splits (+ weight transposes to [N,K])
    split_kernel<<<(TOK_ * H_ / 4 + 255) / 256, 256>>>(hidden, hid_hi, hid_lo, TOK_ * H_ / 4);
    transpose_split_kernel<<<dim3(QKVZW / 32, H_ / 32), 256>>>(w_qkvz, wq_hi, wq_lo, H_, QKVZW);
    transpose_split_kernel<<<dim3(H_ / 32, VDIM_ / 32), 256>>>(w_out, wo_hi, wo_lo, VDIM_, H_);

    // 1) projections
    gemm_bf16s<<<dim3(TOK_ / 128, QKVZW / 128), 256, GSMEM_BYTES>>>(
        hid_hi, hid_lo, wq_hi, wq_lo, qkvz_p, TOK_, QKVZW, H_);
    gemm_ba_kernel<<<TOK_ / 32, 256>>>(hidden, w_ba);

    // 2) conv + activations + norms + gates (+ kq dots)
    qk_conv_norm_kernel<<<dim3(S_, NK_, B_), 128>>>(conv_w);
    v_conv_gate_kernel<<<dim3(S_, NV_, B_), 128>>>(conv_w, dt_bias, A_log);

    // 3) gated delta-rule recurrence
    scan_kernel<<<B_ * NV_ * 4, 128>>>();

    // 4) gated RMSNorm -> split-bf16 y
    rmsnorm_kernel<<<dim3(S_, NV_, B_), 128>>>(norm_w);

    // 5) output projection
    gemm_bf16s<<<dim3(TOK_ / 128, H_ / 128), 256, GSMEM_BYTES>>>(
        y_hi, y_lo, wo_hi, wo_lo, out, TOK_, H_, VDIM_);
}